// round 1
// baseline (speedup 1.0000x reference)
#include <cuda_runtime.h>

// Memory_9835475108444: Hebbian fast-weight scan.
//   p_t = learn * relu6(learn2 * x_t + A_t @ x_t)
//   A_{t+1} = (1-decay) A_t + outer(x_t, p_t)
//   out = relu6(A_T @ x_query)
//
// Low-rank reformulation (exact):
//   A_t = (1-d)^t A_0 + sum_{s<t} (1-d)^{t-1-s} x_s p_s^T
// so A_t @ v = (1-d)^t (A_0 @ v) + sum_{s<t} (1-d)^{t-1-s} (p_s . v) x_s.
// A_0 is read exactly once (64 MiB) for the g_t = A_0 @ x_t terms, with a
// per-row zero fast path (dataset A_init is all zeros -> pure streaming read).

#define BB 256
#define MM 256
#define TT 16
#define NWARP 8

__global__ __launch_bounds__(MM) void memory_fastweight_kernel(
    const float* __restrict__ A0,     // (B, M, M)
    const float* __restrict__ xs,     // (T, B, M)
    const float* __restrict__ xq,     // (B, M)
    const float* __restrict__ pdecay,
    const float* __restrict__ plearn,
    const float* __restrict__ plearn2,
    float* __restrict__ out)          // (B, M)
{
    // Padded to 257 floats/row: conflict-free column-strided accesses.
    __shared__ float sx[TT + 1][MM + 1];  // x_0..x_15, x_query at [TT]
    __shared__ float U[TT + 1][MM + 1];   // g_t, overwritten in-place by p_t; U[TT] = g_q
    __shared__ float sdot[TT];

    const int b    = blockIdx.x;
    const int tid  = threadIdx.x;
    const int lane = tid & 31;
    const int wid  = tid >> 5;

    // ---- load the 17 x-vectors for this batch ----
    #pragma unroll
    for (int t = 0; t < TT; t++)
        sx[t][tid] = xs[(size_t)t * BB * MM + (size_t)b * MM + tid];
    sx[TT][tid] = xq[(size_t)b * MM + tid];
    __syncthreads();

    // ---- phase 1: U[t][row] = sum_j A0[b,row,j] * sx[t][j]  (warp per row) ----
    const float4* Ab = reinterpret_cast<const float4*>(A0 + (size_t)b * MM * MM);
    #pragma unroll 4
    for (int row = wid; row < MM; row += NWARP) {
        const float4* ar = Ab + row * (MM / 4);
        float4 a0 = ar[lane];
        float4 a1 = ar[lane + 32];

        bool nz = (a0.x != 0.f) | (a0.y != 0.f) | (a0.z != 0.f) | (a0.w != 0.f) |
                  (a1.x != 0.f) | (a1.y != 0.f) | (a1.z != 0.f) | (a1.w != 0.f);

        if (__ballot_sync(0xffffffffu, nz) == 0u) {
            // whole row is zero (expected dataset path): g contributions are 0
            if (lane <= TT) U[lane][row] = 0.f;
        } else {
            float acc[TT + 1];
            #pragma unroll
            for (int t = 0; t <= TT; t++) acc[t] = 0.f;
            const int j0 = lane * 4;
            const int j1 = (lane + 32) * 4;
            #pragma unroll
            for (int t = 0; t <= TT; t++) {
                acc[t] += a0.x * sx[t][j0]     + a0.y * sx[t][j0 + 1]
                        + a0.z * sx[t][j0 + 2] + a0.w * sx[t][j0 + 3];
                acc[t] += a1.x * sx[t][j1]     + a1.y * sx[t][j1 + 1]
                        + a1.z * sx[t][j1 + 2] + a1.w * sx[t][j1 + 3];
            }
            #pragma unroll
            for (int t = 0; t <= TT; t++) {
                #pragma unroll
                for (int off = 16; off > 0; off >>= 1)
                    acc[t] += __shfl_down_sync(0xffffffffu, acc[t], off);
            }
            if (lane == 0) {
                #pragma unroll
                for (int t = 0; t <= TT; t++) U[t][row] = acc[t];
            }
        }
    }
    __syncthreads();

    // ---- phase 2: rank-16 recurrence ----
    const float decay  = pdecay[0];
    const float learn  = plearn[0];
    const float learn2 = plearn2[0];
    const float omd    = 1.0f - decay;

    float pw = 1.0f;  // (1-d)^t
    for (int t = 0; t < TT; t++) {
        // sdot[s] = p_s . x_t for s < t   (warps split the s values)
        for (int s = wid; s < t; s += NWARP) {
            float part = 0.f;
            #pragma unroll
            for (int e = 0; e < MM / 32; e++) {
                int j = lane + 32 * e;
                part += U[s][j] * sx[t][j];
            }
            #pragma unroll
            for (int off = 16; off > 0; off >>= 1)
                part += __shfl_down_sync(0xffffffffu, part, off);
            if (lane == 0) sdot[s] = part;
        }
        __syncthreads();

        // Ax_i = (1-d)^t g_t[i] + sum_{s<t} (1-d)^{t-1-s} sdot[s] x_s[i]
        float ax = pw * U[t][tid];
        float c = 1.0f;
        for (int s = t - 1; s >= 0; s--) {
            ax += c * sdot[s] * sx[s][tid];
            c *= omd;
        }
        float v = learn2 * sx[t][tid] + ax;
        v = fminf(fmaxf(v, 0.f), 6.f);
        U[t][tid] = learn * v;       // overwrite g_t with p_t (same thread slot)
        pw *= omd;
        __syncthreads();             // publish p_t (+ sdot reuse) before next step
    }

    // ---- epilogue: out = relu6((1-d)^T g_q + sum_s (1-d)^{T-1-s} (p_s . x_q) x_s) ----
    for (int s = wid; s < TT; s += NWARP) {
        float part = 0.f;
        #pragma unroll
        for (int e = 0; e < MM / 32; e++) {
            int j = lane + 32 * e;
            part += U[s][j] * sx[TT][j];
        }
        #pragma unroll
        for (int off = 16; off > 0; off >>= 1)
            part += __shfl_down_sync(0xffffffffu, part, off);
        if (lane == 0) sdot[s] = part;
    }
    __syncthreads();

    float ax = pw * U[TT][tid];   // pw == (1-d)^T here
    float c = 1.0f;
    for (int s = TT - 1; s >= 0; s--) {
        ax += c * sdot[s] * sx[s][tid];
        c *= omd;
    }
    out[(size_t)b * MM + tid] = fminf(fmaxf(ax, 0.f), 6.f);
}

extern "C" void kernel_launch(void* const* d_in, const int* in_sizes, int n_in,
                              void* d_out, int out_size) {
    const float* A0     = (const float*)d_in[0];
    const float* xs     = (const float*)d_in[1];
    const float* xq     = (const float*)d_in[2];
    const float* decay  = (const float*)d_in[3];
    const float* learn  = (const float*)d_in[4];
    const float* learn2 = (const float*)d_in[5];
    float* out = (float*)d_out;

    memory_fastweight_kernel<<<BB, MM>>>(A0, xs, xq, decay, learn, learn2, out);
}